// round 2
// baseline (speedup 1.0000x reference)
#include <cuda_runtime.h>

#define N1 2048
#define N2 2048
#define D  64

// Scratch (allocation-free rule: __device__ globals)
__device__ float g_qp [N1 * D];   // qp[n][d]   row-major
__device__ float g_kpT[D * N2];   // kp^T[d][m]
__device__ float g_vT [D * N2];   // v^T [d][m]

// ---------------------------------------------------------------------------
// Prep: qp = q@Wq + bq ; kpT = (k@Wk + bk)^T ; vT = v^T
// grid = 3 * 512 blocks of 256 threads, job selected by blockIdx
// ---------------------------------------------------------------------------
__global__ void prep_kernel(const float* __restrict__ q,
                            const float* __restrict__ k,
                            const float* __restrict__ v,
                            const float* __restrict__ Wq, const float* __restrict__ bq,
                            const float* __restrict__ Wk, const float* __restrict__ bk) {
    int job = blockIdx.x / 512;
    int i   = (blockIdx.x % 512) * 256 + threadIdx.x;   // 0 .. 131071
    int n   = i >> 6;
    int d   = i & 63;

    if (job == 2) {                       // v transpose
        g_vT[d * N2 + n] = v[i];
        return;
    }
    const float* x = (job == 0) ? q  : k;
    const float* W = (job == 0) ? Wq : Wk;
    float acc = 0.f;
#pragma unroll
    for (int kk = 0; kk < D; kk++)
        acc = fmaf(x[n * D + kk], W[kk * D + d], acc);
    if (job == 0) g_qp[i] = acc + bq[d];
    else          g_kpT[d * N2 + n] = acc + bk[d];
}

// ---------------------------------------------------------------------------
// Main fused kernel: scores + softmax + P@V
// 256 blocks x 256 threads. Block = 8 query rows (warp <-> row).
// Lanes cover a 64-wide m tile (2 scores per lane per tile).
// Scores are bounded (|s| <= sum|w| + |b| ~ 3) -> no running-max needed.
// ---------------------------------------------------------------------------
__global__ __launch_bounds__(256, 2)
void attn_kernel(const float* __restrict__ wvec,
                 const float* __restrict__ bptr,
                 float* __restrict__ out,          // [N1, D]
                 float* __restrict__ att_score) {  // [N1, N2]
    __shared__ float kTs[D][64];   // k^T tile: [d][m]  (lane reads consec m: no conflicts)
    __shared__ float vTs[D][64];   // v^T tile
    __shared__ float qs [8][D];    // qp rows of this block
    __shared__ float ws [D];

    const int tid  = threadIdx.x;
    const int warp = tid >> 5;
    const int lane = tid & 31;
    const int n0   = blockIdx.x * 8;
    const int n    = n0 + warp;

    // stage qp rows (negated: feeds exp(-(q+k)) without per-element negate) + w
    ((float*)qs)[tid]       = -g_qp[n0 * D + tid];
    ((float*)qs)[tid + 256] = -g_qp[n0 * D + tid + 256];
    if (tid < D) ws[tid] = wvec[tid];
    const float b0 = bptr[0];

    float acc[D];
#pragma unroll
    for (int d = 0; d < D; d++) acc[d] = 0.f;
    float S = 0.f;

    float* score_row = att_score + (size_t)n * N2;

    for (int t = 0; t < N2 / 64; t++) {
        __syncthreads();   // previous tile fully consumed (also orders qs/ws on t==0)
        {
            // cooperative coalesced tile load: 64x64 floats each, 4x float4/thread
            int r    = tid >> 4;            // 0..15
            int c    = (tid & 15) << 2;     // 0..60
            int col0 = t * 64;
#pragma unroll
            for (int j = 0; j < 4; j++) {
                int rr = r + j * 16;
                *(float4*)&kTs[rr][c] = *(const float4*)&g_kpT[rr * N2 + col0 + c];
                *(float4*)&vTs[rr][c] = *(const float4*)&g_vT [rr * N2 + col0 + c];
            }
        }
        __syncthreads();

        // ----- scores: s = sum_d w[d] * sigmoid(q[d]+k[d]) -----
        float s0 = 0.f, s1 = 0.f;
#pragma unroll 16
        for (int d = 0; d < D; d++) {
            float nqd = qs[warp][d];    // warp-uniform broadcast, already negated
            float wd  = ws[d];
            float x0 = nqd - kTs[d][lane];        // -(q+k)
            float x1 = nqd - kTs[d][lane + 32];
            s0 += __fdividef(wd, 1.f + __expf(x0));
            s1 += __fdividef(wd, 1.f + __expf(x1));
        }
        s0 += b0; s1 += b0;
        score_row[t * 64 + lane]      = s0;
        score_row[t * 64 + 32 + lane] = s1;

        // ----- softmax accumulation (no max: scores bounded ~|3|) -----
        float p0 = __expf(s0);
        float p1 = __expf(s1);
        S += p0 + p1;
#pragma unroll
        for (int d = 0; d < D; d++)
            acc[d] += p0 * vTs[d][lane] + p1 * vTs[d][lane + 32];
    }

    // ----- warp reductions over lanes (each lane held a partial over its m's) -----
#pragma unroll
    for (int off = 16; off; off >>= 1)
        S += __shfl_xor_sync(0xffffffffu, S, off);
#pragma unroll
    for (int d = 0; d < D; d++) {
#pragma unroll
        for (int off = 16; off; off >>= 1)
            acc[d] += __shfl_xor_sync(0xffffffffu, acc[d], off);
    }
    float rS = __fdividef(1.f, S);

    if (lane == 0) {
        float* orow = out + n * D;
#pragma unroll
        for (int d = 0; d < D; d += 4) {
            float4 o = make_float4(acc[d] * rS, acc[d + 1] * rS,
                                   acc[d + 2] * rS, acc[d + 3] * rS);
            *(float4*)&orow[d] = o;
        }
    }
}

// ---------------------------------------------------------------------------
extern "C" void kernel_launch(void* const* d_in, const int* in_sizes, int n_in,
                              void* d_out, int out_size) {
    const float* q  = (const float*)d_in[0];
    const float* k  = (const float*)d_in[1];
    const float* v  = (const float*)d_in[2];
    const float* Wq = (const float*)d_in[3];
    const float* bq = (const float*)d_in[4];
    const float* Wk = (const float*)d_in[5];
    const float* bk = (const float*)d_in[6];
    const float* w  = (const float*)d_in[7];
    const float* b  = (const float*)d_in[8];

    float* out       = (float*)d_out;          // [N1, D] first
    float* att_score = out + N1 * D;           // then [N1, N2]

    prep_kernel<<<3 * 512, 256>>>(q, k, v, Wq, bq, Wk, bk);
    attn_kernel<<<N1 / 8, 256>>>(w, b, out, att_score);
}

// round 4
// speedup vs baseline: 1.3053x; 1.3053x over previous
#include <cuda_runtime.h>

#define N1 2048
#define N2 2048
#define D  64

// Scratch (allocation-free rule: __device__ globals)
__device__ float g_qph[N1 * D];   // 0.5*(q@Wq+bq)   row-major [n][d]
__device__ float g_kpTh[D * N2];  // 0.5*(k@Wk+bk)^T [d][m]
__device__ float g_vT [D * N2];   // v^T             [d][m]

__device__ __forceinline__ float tanh_fast(float x) {
    float y;
    asm("tanh.approx.f32 %0, %1;" : "=f"(y) : "f"(x));
    return y;
}

// ---------------------------------------------------------------------------
// Prep: halved projections + v transpose
// ---------------------------------------------------------------------------
__global__ void prep_kernel(const float* __restrict__ q,
                            const float* __restrict__ k,
                            const float* __restrict__ v,
                            const float* __restrict__ Wq, const float* __restrict__ bq,
                            const float* __restrict__ Wk, const float* __restrict__ bk) {
    int job = blockIdx.x / 512;
    int i   = (blockIdx.x % 512) * 256 + threadIdx.x;   // 0 .. 131071
    int n   = i >> 6;
    int d   = i & 63;

    if (job == 2) {                       // v transpose
        g_vT[d * N2 + n] = v[i];
        return;
    }
    const float* x = (job == 0) ? q  : k;
    const float* W = (job == 0) ? Wq : Wk;
    float acc = 0.f;
#pragma unroll
    for (int kk = 0; kk < D; kk++)
        acc = fmaf(x[n * D + kk], W[kk * D + d], acc);
    if (job == 0) g_qph[i] = 0.5f * (acc + bq[d]);
    else          g_kpTh[d * N2 + n] = 0.5f * (acc + bk[d]);
}

// ---------------------------------------------------------------------------
// Main fused kernel. Block = 8 query rows (warp <-> row), 64-wide m tiles.
// Lane handles m = 2*lane, 2*lane+1 (float2 smem ops).
// sigmoid(z) = 0.5*tanh(z/2)+0.5 folded:
//   s = sum_d (w_d/2)*tanh(q_d/2 + k_d/2) + (b + sum_d w_d/2)
// ---------------------------------------------------------------------------
__global__ __launch_bounds__(256, 2)
void attn_kernel(const float* __restrict__ wvec,
                 const float* __restrict__ bptr,
                 float* __restrict__ out,          // [N1, D]
                 float* __restrict__ att_score) {  // [N1, N2]
    __shared__ float  kTs[D][64];      // k^T/2 tile [d][m]
    __shared__ float  vTs[D][64];      // v^T   tile [d][m]
    __shared__ float4 qw4[8][32];      // (qh[2e], wh[2e], qh[2e+1], wh[2e+1]) per warp

    const int tid  = threadIdx.x;
    const int warp = tid >> 5;
    const int lane = tid & 31;
    const int n0   = blockIdx.x * 8;
    const int n    = n0 + warp;

    // stage interleaved (q/2, w/2) pairs: one float4 per (warp,d-pair)
    {
        int wi = tid >> 5, e = tid & 31;                    // 256 entries total
        float2 qv = ((const float2*)(g_qph + (n0 + wi) * D))[e];
        float  w0 = 0.5f * wvec[2 * e];
        float  w1 = 0.5f * wvec[2 * e + 1];
        qw4[wi][e] = make_float4(qv.x, w0, qv.y, w1);
    }
    __syncthreads();

    // bias = b + sum_d w_d/2   (from staged smem, one-time)
    float bias;
    {
        float wsum = 0.f;
#pragma unroll
        for (int e = 0; e < 32; e++) {
            float4 qw = qw4[warp][e];
            wsum += qw.y + qw.w;
        }
        bias = bptr[0] + wsum;
    }

    float acc[D];
#pragma unroll
    for (int d = 0; d < D; d++) acc[d] = 0.f;
    float S = 0.f;

    float2* score_row2 = (float2*)(att_score + (size_t)n * N2);

    for (int t = 0; t < N2 / 64; t++) {
        {
            // cooperative coalesced tile load: 64x64 floats each, 4x float4/thread
            int r    = tid >> 4;            // 0..15
            int c    = (tid & 15) << 2;     // 0..60
            int col0 = t * 64;
#pragma unroll
            for (int j = 0; j < 4; j++) {
                int rr = r + j * 16;
                *(float4*)&kTs[rr][c] = *(const float4*)&g_kpTh[rr * N2 + col0 + c];
                *(float4*)&vTs[rr][c] = *(const float4*)&g_vT  [rr * N2 + col0 + c];
            }
        }
        __syncthreads();

        // ----- scores (two d per iter, float4 uniform broadcast) -----
        float s0 = 0.f, s1 = 0.f;
#pragma unroll 8
        for (int e = 0; e < 32; e++) {
            float4 qw = qw4[warp][e];
            float2 k0 = ((const float2*)kTs[2 * e    ])[lane];
            float2 k1 = ((const float2*)kTs[2 * e + 1])[lane];
            float t00 = tanh_fast(qw.x + k0.x);
            float t01 = tanh_fast(qw.x + k0.y);
            float t10 = tanh_fast(qw.z + k1.x);
            float t11 = tanh_fast(qw.z + k1.y);
            s0 = fmaf(qw.y, t00, s0);
            s1 = fmaf(qw.y, t01, s1);
            s0 = fmaf(qw.w, t10, s0);
            s1 = fmaf(qw.w, t11, s1);
        }
        s0 += bias; s1 += bias;
        score_row2[t * 32 + lane] = make_float2(s0, s1);

        // ----- softmax accumulation (scores bounded ~|3|: no running max) -----
        float p0 = __expf(s0);
        float p1 = __expf(s1);
        S += p0 + p1;
#pragma unroll
        for (int d = 0; d < D; d++) {
            float2 vv = ((const float2*)vTs[d])[lane];
            acc[d] = fmaf(p0, vv.x, fmaf(p1, vv.y, acc[d]));
        }
        __syncthreads();   // tile consumed before next overwrite
    }

    // ----- warp reductions over lanes -----
#pragma unroll
    for (int off = 16; off; off >>= 1)
        S += __shfl_xor_sync(0xffffffffu, S, off);
#pragma unroll
    for (int d = 0; d < D; d++) {
#pragma unroll
        for (int off = 16; off; off >>= 1)
            acc[d] += __shfl_xor_sync(0xffffffffu, acc[d], off);
    }
    float rS = __fdividef(1.f, S);

    if (lane == 0) {
        float* orow = out + n * D;
#pragma unroll
        for (int d = 0; d < D; d += 4) {
            float4 o = make_float4(acc[d] * rS, acc[d + 1] * rS,
                                   acc[d + 2] * rS, acc[d + 3] * rS);
            *(float4*)&orow[d] = o;
        }
    }
}

// ---------------------------------------------------------------------------
extern "C" void kernel_launch(void* const* d_in, const int* in_sizes, int n_in,
                              void* d_out, int out_size) {
    const float* q  = (const float*)d_in[0];
    const float* k  = (const float*)d_in[1];
    const float* v  = (const float*)d_in[2];
    const float* Wq = (const float*)d_in[3];
    const float* bq = (const float*)d_in[4];
    const float* Wk = (const float*)d_in[5];
    const float* bk = (const float*)d_in[6];
    const float* w  = (const float*)d_in[7];
    const float* b  = (const float*)d_in[8];

    float* out       = (float*)d_out;          // [N1, D] first
    float* att_score = out + N1 * D;           // then [N1, N2]

    prep_kernel<<<3 * 512, 256>>>(q, k, v, Wq, bq, Wk, bk);
    attn_kernel<<<N1 / 8, 256>>>(w, b, out, att_score);
}

// round 5
// speedup vs baseline: 1.5675x; 1.2008x over previous
#include <cuda_runtime.h>
#include <cstdint>

#define N1   2048
#define N2   2048
#define D    64
#define TILE 64
#define NT   (N2 / TILE)   // 32

// Scratch (allocation-free rule: __device__ globals)
__device__ float g_qph [N1 * D];   // 0.5*(q@Wq+bq)   row-major [n][d]
__device__ float g_kpTh[D * N2];   // 0.5*(k@Wk+bk)^T [d][m]
__device__ float g_vT  [D * N2];   // v^T             [d][m]

__device__ __forceinline__ float tanh_fast(float x) {
    float y;
    asm("tanh.approx.f32 %0, %1;" : "=f"(y) : "f"(x));
    return y;
}
__device__ __forceinline__ void cp_async16(void* saddr, const void* gptr) {
    uint32_t s = (uint32_t)__cvta_generic_to_shared(saddr);
    asm volatile("cp.async.cg.shared.global [%0], [%1], 16;" :: "r"(s), "l"(gptr));
}
__device__ __forceinline__ void cp_commit() { asm volatile("cp.async.commit_group;"); }
__device__ __forceinline__ void cp_wait0()  { asm volatile("cp.async.wait_group 0;" ::: "memory"); }

// ---------------------------------------------------------------------------
// Prep: halved projections + v transpose
// ---------------------------------------------------------------------------
__global__ void prep_kernel(const float* __restrict__ q,
                            const float* __restrict__ k,
                            const float* __restrict__ v,
                            const float* __restrict__ Wq, const float* __restrict__ bq,
                            const float* __restrict__ Wk, const float* __restrict__ bk) {
    int job = blockIdx.x / 512;
    int i   = (blockIdx.x % 512) * 256 + threadIdx.x;   // 0 .. 131071
    int n   = i >> 6;
    int d   = i & 63;

    if (job == 2) {                       // v transpose
        g_vT[d * N2 + n] = v[i];
        return;
    }
    const float* x = (job == 0) ? q  : k;
    const float* W = (job == 0) ? Wq : Wk;
    float acc = 0.f;
#pragma unroll
    for (int kk = 0; kk < D; kk++)
        acc = fmaf(x[n * D + kk], W[kk * D + d], acc);
    if (job == 0) g_qph[i] = 0.5f * (acc + bq[d]);
    else          g_kpTh[d * N2 + n] = 0.5f * (acc + bk[d]);
}

// ---------------------------------------------------------------------------
// Main fused kernel. Block = 16 query rows, 8 warps, warp <-> 2 rows.
// Lane handles m = 2*lane, 2*lane+1. Each k/v smem read feeds BOTH rows.
// Double-buffered tiles via cp.async (one barrier per tile).
// sigmoid(z) = 0.5*tanh(z/2)+0.5 folded:
//   s = sum_d (w_d/2)*tanh(q_d/2 + k_d/2) + (b + sum_d w_d/2)
// ---------------------------------------------------------------------------
__global__ __launch_bounds__(256, 1)
void attn_kernel(const float* __restrict__ wvec,
                 const float* __restrict__ bptr,
                 float* __restrict__ out,          // [N1, D]
                 float* __restrict__ att_score) {  // [N1, N2]
    extern __shared__ float sm[];
    // layout: [k0 4096][v0 4096][k1 4096][v1 4096][qws 2048 floats]
    float*  kb0 = sm;
    float*  vb0 = sm + 4096;
    float*  kb1 = sm + 8192;
    float*  vb1 = sm + 12288;
    float4* qws = (float4*)(sm + 16384);   // [8 warps][64 d]: (q_r0/2, q_r1/2, w/2, -)

    const int tid  = threadIdx.x;
    const int warp = tid >> 5;
    const int lane = tid & 31;
    const int n0   = blockIdx.x * 16;
    const int r0   = n0 + 2 * warp;
    const int r1   = r0 + 1;

    // stage (q rows)/2 + w/2 interleaved per warp
    for (int i = tid; i < 512; i += 256) {
        int wi = i >> 6, d = i & 63;
        int rr = n0 + 2 * wi;
        qws[i] = make_float4(g_qph[rr * D + d], g_qph[(rr + 1) * D + d],
                             0.5f * wvec[d], 0.f);
    }
    // prologue: async-load tile 0 into buffer 0
    {
        int r = tid >> 4, c = (tid & 15) << 2;
#pragma unroll
        for (int j = 0; j < 4; j++) {
            int rr = r + j * 16;
            cp_async16(kb0 + rr * 64 + c, g_kpTh + rr * N2 + c);
            cp_async16(vb0 + rr * 64 + c, g_vT   + rr * N2 + c);
        }
        cp_commit();
    }
    __syncthreads();   // qws visible

    // bias = b + sum_d w_d/2
    float bias = bptr[0];
#pragma unroll
    for (int d = 0; d < D; d++) bias += qws[warp * 64 + d].z;

    float a0[D], a1[D];
#pragma unroll
    for (int d = 0; d < D; d++) { a0[d] = 0.f; a1[d] = 0.f; }
    float S0 = 0.f, S1 = 0.f;

    float2* sr0 = (float2*)(att_score + (size_t)r0 * N2);
    float2* sr1 = (float2*)(att_score + (size_t)r1 * N2);

    for (int t = 0; t < NT; t++) {
        cp_wait0();
        __syncthreads();   // this tile's buffer filled; prev tile's compute done by all

        const float* kt = (t & 1) ? kb1 : kb0;
        const float* vt = (t & 1) ? vb1 : vb0;

        if (t + 1 < NT) {  // async-load next tile into the other buffer
            float* kn = (t & 1) ? kb0 : kb1;
            float* vn = (t & 1) ? vb0 : vb1;
            int r = tid >> 4, c = (tid & 15) << 2;
            int col0 = (t + 1) * 64;
#pragma unroll
            for (int j = 0; j < 4; j++) {
                int rr = r + j * 16;
                cp_async16(kn + rr * 64 + c, g_kpTh + rr * N2 + col0 + c);
                cp_async16(vn + rr * 64 + c, g_vT   + rr * N2 + col0 + c);
            }
            cp_commit();
        }

        // ----- scores: 1 LDS.64 of k feeds 2 rows x 2 m -----
        float s00 = 0.f, s01 = 0.f, s10 = 0.f, s11 = 0.f;
#pragma unroll 16
        for (int d = 0; d < D; d++) {
            float4 qw = qws[warp * 64 + d];                 // uniform broadcast
            float2 kk = ((const float2*)(kt + d * 64))[lane];
            float t00 = tanh_fast(qw.x + kk.x);
            float t01 = tanh_fast(qw.x + kk.y);
            float t10 = tanh_fast(qw.y + kk.x);
            float t11 = tanh_fast(qw.y + kk.y);
            s00 = fmaf(qw.z, t00, s00);
            s01 = fmaf(qw.z, t01, s01);
            s10 = fmaf(qw.z, t10, s10);
            s11 = fmaf(qw.z, t11, s11);
        }
        s00 += bias; s01 += bias; s10 += bias; s11 += bias;
        sr0[t * 32 + lane] = make_float2(s00, s01);
        sr1[t * 32 + lane] = make_float2(s10, s11);

        // ----- softmax accumulation (scores bounded ~|3|: no running max) -----
        float p00 = __expf(s00), p01 = __expf(s01);
        float p10 = __expf(s10), p11 = __expf(s11);
        S0 += p00 + p01;
        S1 += p10 + p11;

        // ----- P@V: 1 LDS.64 of v feeds 2 rows -----
#pragma unroll
        for (int d = 0; d < D; d++) {
            float2 vv = ((const float2*)(vt + d * 64))[lane];
            a0[d] = fmaf(p00, vv.x, fmaf(p01, vv.y, a0[d]));
            a1[d] = fmaf(p10, vv.x, fmaf(p11, vv.y, a1[d]));
        }
        // no trailing sync: next iteration's barrier protects buffer reuse
    }

    // ----- warp reductions over lanes -----
#pragma unroll
    for (int off = 16; off; off >>= 1) {
        S0 += __shfl_xor_sync(0xffffffffu, S0, off);
        S1 += __shfl_xor_sync(0xffffffffu, S1, off);
    }
#pragma unroll
    for (int d = 0; d < D; d++) {
#pragma unroll
        for (int off = 16; off; off >>= 1) {
            a0[d] += __shfl_xor_sync(0xffffffffu, a0[d], off);
            a1[d] += __shfl_xor_sync(0xffffffffu, a1[d], off);
        }
    }
    float i0 = __fdividef(1.f, S0);
    float i1 = __fdividef(1.f, S1);

    if (lane == 0) {
        float* orow = out + r0 * D;
#pragma unroll
        for (int d = 0; d < D; d += 4)
            *(float4*)&orow[d] = make_float4(a0[d] * i0, a0[d + 1] * i0,
                                             a0[d + 2] * i0, a0[d + 3] * i0);
    }
    if (lane == 1) {
        float* orow = out + r1 * D;
#pragma unroll
        for (int d = 0; d < D; d += 4)
            *(float4*)&orow[d] = make_float4(a1[d] * i1, a1[d + 1] * i1,
                                             a1[d + 2] * i1, a1[d + 3] * i1);
    }
}

// ---------------------------------------------------------------------------
extern "C" void kernel_launch(void* const* d_in, const int* in_sizes, int n_in,
                              void* d_out, int out_size) {
    const float* q  = (const float*)d_in[0];
    const float* k  = (const float*)d_in[1];
    const float* v  = (const float*)d_in[2];
    const float* Wq = (const float*)d_in[3];
    const float* bq = (const float*)d_in[4];
    const float* Wk = (const float*)d_in[5];
    const float* bk = (const float*)d_in[6];
    const float* w  = (const float*)d_in[7];
    const float* b  = (const float*)d_in[8];

    float* out       = (float*)d_out;          // [N1, D] first
    float* att_score = out + N1 * D;           // then [N1, N2]

    const int SMEM_BYTES = (4 * 4096 + 2048) * (int)sizeof(float);   // 73728
    cudaFuncSetAttribute(attn_kernel, cudaFuncAttributeMaxDynamicSharedMemorySize,
                         SMEM_BYTES);

    prep_kernel<<<3 * 512, 256>>>(q, k, v, Wq, bq, Wk, bk);
    attn_kernel<<<N1 / 16, 256, SMEM_BYTES>>>(w, b, out, att_score);
}

// round 6
// speedup vs baseline: 1.6795x; 1.0715x over previous
#include <cuda_runtime.h>
#include <cstdint>

#define N1    2048
#define N2    2048
#define D     64
#define TILE  64
#define HALF  (N2 / 2)        // 1024
#define NT2   (HALF / TILE)   // 16 tiles per block

// Scratch (allocation-free rule: __device__ globals)
__device__ float g_qph [N1 * D];        // 0.5*(q@Wq+bq)   row-major [n][d]
__device__ float g_kpTh[D * N2];        // 0.5*(k@Wk+bk)^T [d][m]
__device__ float g_accP[2 * N1 * D];    // partial PV accumulators per half
__device__ float g_Ssum[2 * N1];        // partial exp-sums per half

__device__ __forceinline__ float tanh_fast(float x) {
    float y;
    asm("tanh.approx.f32 %0, %1;" : "=f"(y) : "f"(x));
    return y;
}
__device__ __forceinline__ void cp_async16(void* saddr, const void* gptr) {
    uint32_t s = (uint32_t)__cvta_generic_to_shared(saddr);
    asm volatile("cp.async.cg.shared.global [%0], [%1], 16;" :: "r"(s), "l"(gptr));
}
__device__ __forceinline__ void cp_commit() { asm volatile("cp.async.commit_group;"); }
__device__ __forceinline__ void cp_wait0()  { asm volatile("cp.async.wait_group 0;" ::: "memory"); }

// ---------------------------------------------------------------------------
// Prep: halved projections (no v transpose needed anymore)
// ---------------------------------------------------------------------------
__global__ void prep_kernel(const float* __restrict__ q,
                            const float* __restrict__ k,
                            const float* __restrict__ Wq, const float* __restrict__ bq,
                            const float* __restrict__ Wk, const float* __restrict__ bk) {
    int job = blockIdx.x / 512;
    int i   = (blockIdx.x % 512) * 256 + threadIdx.x;   // 0 .. 131071
    int n   = i >> 6;
    int d   = i & 63;

    const float* x = (job == 0) ? q  : k;
    const float* W = (job == 0) ? Wq : Wk;
    float acc = 0.f;
#pragma unroll
    for (int kk = 0; kk < D; kk++)
        acc = fmaf(x[n * D + kk], W[kk * D + d], acc);
    if (job == 0) g_qph[i] = 0.5f * (acc + bq[d]);
    else          g_kpTh[d * N2 + n] = 0.5f * (acc + bk[d]);
}

// ---------------------------------------------------------------------------
// Main fused kernel. Grid = 256: (row-group 0..127) x (m-half 0..1).
// Block 256 thr = 8 warps x 2 rows = 16 rows; each block does HALF of N2.
// Score phase: lane handles m-pair; k smem read feeds 2 rows x 2 m.
// PV phase: p staged in warp-private smem; lane owns a d-pair (acc = 4 regs).
// sigmoid(z) = 0.5*tanh(z/2)+0.5 folded into halved inputs + bias.
// ---------------------------------------------------------------------------
__global__ __launch_bounds__(256, 2)
void attn_kernel(const float* __restrict__ vglob,    // [N2, D] original v
                 const float* __restrict__ wvec,
                 const float* __restrict__ bptr,
                 float* __restrict__ att_score) {    // [N1, N2]
    extern __shared__ float sm[];
    // layout (floats): [k0 4096][v0 4096][k1 4096][v1 4096][qws 2048][p 1024]
    float*  kb0 = sm;
    float*  vb0 = sm + 4096;
    float*  kb1 = sm + 8192;
    float*  vb1 = sm + 12288;
    float4* qws = (float4*)(sm + 16384);   // [8 warps][64 d]: (q_r0/2, q_r1/2, w/2, 0)
    float*  psm = sm + 18432;              // [8 warps][64 m][2 rows]

    const int tid   = threadIdx.x;
    const int warp  = tid >> 5;
    const int lane  = tid & 31;
    const int half  = blockIdx.x & 1;
    const int n0    = (blockIdx.x >> 1) * 16;
    const int r0    = n0 + 2 * warp;
    const int r1    = r0 + 1;
    const int mbase = half * HALF;

    // stage (q rows)/2 + w/2 interleaved per warp
    for (int i = tid; i < 512; i += 256) {
        int wi = i >> 6, d = i & 63;
        int rr = n0 + 2 * wi;
        qws[i] = make_float4(g_qph[rr * D + d], g_qph[(rr + 1) * D + d],
                             0.5f * wvec[d], 0.f);
    }
    // prologue: async-load tile 0 (k transposed-half, v original layout)
    {
        int r = tid >> 4, c = (tid & 15) << 2;
#pragma unroll
        for (int j = 0; j < 4; j++) {
            int rr = r + j * 16;
            cp_async16(kb0 + rr * 64 + c, g_kpTh + rr * N2 + mbase + c);
            cp_async16(vb0 + rr * 64 + c, vglob + (mbase + rr) * D + c);
        }
        cp_commit();
    }
    __syncthreads();   // qws visible

    // bias = b + sum_d w_d/2
    float bias = bptr[0];
#pragma unroll
    for (int d = 0; d < D; d++) bias += qws[warp * 64 + d].z;

    float2 a0 = make_float2(0.f, 0.f);   // acc for row r0, d = 2*lane, 2*lane+1
    float2 a1 = make_float2(0.f, 0.f);   // acc for row r1
    float  S0 = 0.f, S1 = 0.f;

    float2* sr0 = (float2*)(att_score + (size_t)r0 * N2 + mbase);
    float2* sr1 = (float2*)(att_score + (size_t)r1 * N2 + mbase);
    float*  pw  = psm + warp * 128;      // this warp's p staging [64 m][2 rows]

    for (int t = 0; t < NT2; t++) {
        cp_wait0();
        __syncthreads();   // tile buffer filled; prev tile consumed by all warps

        const float* kt = (t & 1) ? kb1 : kb0;
        const float* vt = (t & 1) ? vb1 : vb0;

        if (t + 1 < NT2) {  // async-load next tile into the other buffer
            float* kn = (t & 1) ? kb0 : kb1;
            float* vn = (t & 1) ? vb0 : vb1;
            int r = tid >> 4, c = (tid & 15) << 2;
            int col0 = mbase + (t + 1) * 64;
#pragma unroll
            for (int j = 0; j < 4; j++) {
                int rr = r + j * 16;
                cp_async16(kn + rr * 64 + c, g_kpTh + rr * N2 + col0 + c);
                cp_async16(vn + rr * 64 + c, vglob + (col0 + rr) * D + c);
            }
            cp_commit();
        }

        // ----- scores: 1 LDS.64 of k feeds 2 rows x 2 m -----
        float s00 = 0.f, s01 = 0.f, s10 = 0.f, s11 = 0.f;
#pragma unroll 8
        for (int d = 0; d < D; d++) {
            float4 qw = qws[warp * 64 + d];                 // uniform broadcast
            float2 kk = ((const float2*)(kt + d * 64))[lane];
            float t00 = tanh_fast(qw.x + kk.x);
            float t01 = tanh_fast(qw.x + kk.y);
            float t10 = tanh_fast(qw.y + kk.x);
            float t11 = tanh_fast(qw.y + kk.y);
            s00 = fmaf(qw.z, t00, s00);
            s01 = fmaf(qw.z, t01, s01);
            s10 = fmaf(qw.z, t10, s10);
            s11 = fmaf(qw.z, t11, s11);
        }
        s00 += bias; s01 += bias; s10 += bias; s11 += bias;
        sr0[t * 32 + lane] = make_float2(s00, s01);
        sr1[t * 32 + lane] = make_float2(s10, s11);

        // ----- softmax weights (scores bounded ~|3|: no running max) -----
        float p00 = __expf(s00), p01 = __expf(s01);
        float p10 = __expf(s10), p11 = __expf(s11);
        S0 += p00 + p01;
        S1 += p10 + p11;

        // stage p in warp-private smem: [m][2 rows]
        ((float2*)pw)[2 * lane]     = make_float2(p00, p10);
        ((float2*)pw)[2 * lane + 1] = make_float2(p01, p11);
        __syncwarp();

        // ----- PV: lane owns d-pair; p uniform broadcast, v conflict-free -----
#pragma unroll 8
        for (int m = 0; m < TILE; m++) {
            float2 pp = ((const float2*)pw)[m];             // (p_r0[m], p_r1[m])
            float2 vv = ((const float2*)(vt + m * 64))[lane];
            a0.x = fmaf(pp.x, vv.x, a0.x);
            a0.y = fmaf(pp.x, vv.y, a0.y);
            a1.x = fmaf(pp.y, vv.x, a1.x);
            a1.y = fmaf(pp.y, vv.y, a1.y);
        }
        __syncwarp();   // p buffer fully consumed before next tile overwrites
    }

    // ----- S reduction over lanes (acc needs none: d-owned) -----
#pragma unroll
    for (int off = 16; off; off >>= 1) {
        S0 += __shfl_xor_sync(0xffffffffu, S0, off);
        S1 += __shfl_xor_sync(0xffffffffu, S1, off);
    }

    // partial results to scratch
    ((float2*)(g_accP + ((size_t)half * N1 + r0) * D))[lane] = a0;
    ((float2*)(g_accP + ((size_t)half * N1 + r1) * D))[lane] = a1;
    if (lane == 0) {
        g_Ssum[half * N1 + r0] = S0;
        g_Ssum[half * N1 + r1] = S1;
    }
}

// ---------------------------------------------------------------------------
// Combine halves: out[n][d] = (accA + accB) / (SA + SB)
// ---------------------------------------------------------------------------
__global__ void combine_kernel(float* __restrict__ out) {
    int tid = threadIdx.x;
    int n   = blockIdx.x * 8 + (tid >> 5);
    int d2  = tid & 31;
    float2 A = ((const float2*)(g_accP + (size_t)n * D))[d2];
    float2 B = ((const float2*)(g_accP + ((size_t)N1 + n) * D))[d2];
    float  r = __fdividef(1.f, g_Ssum[n] + g_Ssum[N1 + n]);
    ((float2*)(out + (size_t)n * D))[d2] =
        make_float2((A.x + B.x) * r, (A.y + B.y) * r);
}

// ---------------------------------------------------------------------------
extern "C" void kernel_launch(void* const* d_in, const int* in_sizes, int n_in,
                              void* d_out, int out_size) {
    const float* q  = (const float*)d_in[0];
    const float* k  = (const float*)d_in[1];
    const float* v  = (const float*)d_in[2];
    const float* Wq = (const float*)d_in[3];
    const float* bq = (const float*)d_in[4];
    const float* Wk = (const float*)d_in[5];
    const float* bk = (const float*)d_in[6];
    const float* w  = (const float*)d_in[7];
    const float* b  = (const float*)d_in[8];

    float* out       = (float*)d_out;          // [N1, D] first
    float* att_score = out + N1 * D;           // then [N1, N2]

    const int SMEM_BYTES = (4 * 4096 + 2048 + 1024) * (int)sizeof(float);   // 77824
    cudaFuncSetAttribute(attn_kernel, cudaFuncAttributeMaxDynamicSharedMemorySize,
                         SMEM_BYTES);

    prep_kernel<<<2 * 512, 256>>>(q, k, Wq, bq, Wk, bk);
    attn_kernel<<<256, 256, SMEM_BYTES>>>(v, w, b, att_score);
    combine_kernel<<<N1 / 8, 256>>>(out);
}

// round 8
// speedup vs baseline: 1.9150x; 1.1402x over previous
#include <cuda_runtime.h>
#include <cstdint>

#define N1     2048
#define N2     2048
#define D      64
#define TILE   64
#define SPLITS 8
#define SPAN   (N2 / SPLITS)     // 256 m per block
#define NT     (SPAN / TILE)     // 4 tiles per block

// Scratch (allocation-free rule: __device__ globals)
__device__ float  g_qph [N1 * D];          // 0.5*(q@Wq+bq)   row-major [n][d]
__device__ float  g_kpTh[D * N2];          // 0.5*(k@Wk+bk)^T [d][m]
__device__ float4 g_qw4 [(N1 / 2) * D];    // (q_2p/2, q_2p+1/2, w/2, 0)
__device__ float  g_bias;                  // b + sum_d w_d/2
__device__ float  g_accP[SPLITS * N1 * D]; // partial PV accumulators
__device__ float  g_Ssum[SPLITS * N1];     // partial exp-sums

__device__ __forceinline__ float tanh_fast(float x) {
    float y;
    asm("tanh.approx.f32 %0, %1;" : "=f"(y) : "f"(x));
    return y;
}
__device__ __forceinline__ void cp_async16(void* saddr, const void* gptr) {
    uint32_t s = (uint32_t)__cvta_generic_to_shared(saddr);
    asm volatile("cp.async.cg.shared.global [%0], [%1], 16;" :: "r"(s), "l"(gptr));
}
__device__ __forceinline__ void cp_commit() { asm volatile("cp.async.commit_group;"); }
__device__ __forceinline__ void cp_wait0()  { asm volatile("cp.async.wait_group 0;" ::: "memory"); }

// ---------------------------------------------------------------------------
// Prep: halved projections
// ---------------------------------------------------------------------------
__global__ void prep_kernel(const float* __restrict__ q,
                            const float* __restrict__ k,
                            const float* __restrict__ Wq, const float* __restrict__ bq,
                            const float* __restrict__ Wk, const float* __restrict__ bk) {
    int job = blockIdx.x / 512;
    int i   = (blockIdx.x % 512) * 256 + threadIdx.x;   // 0 .. 131071
    int n   = i >> 6;
    int d   = i & 63;

    const float* x = (job == 0) ? q  : k;
    const float* W = (job == 0) ? Wq : Wk;
    float acc = 0.f;
#pragma unroll
    for (int kk = 0; kk < D; kk++)
        acc = fmaf(x[n * D + kk], W[kk * D + d], acc);
    if (job == 0) g_qph[i] = 0.5f * (acc + bq[d]);
    else          g_kpTh[d * N2 + n] = 0.5f * (acc + bk[d]);
}

// ---------------------------------------------------------------------------
// Prep2: interleaved (q-pair, w) float4 table + scalar bias
// ---------------------------------------------------------------------------
__global__ void prep2_kernel(const float* __restrict__ wvec,
                             const float* __restrict__ bptr) {
    int i = blockIdx.x * 256 + threadIdx.x;   // 0 .. 65535
    int p = i >> 6;
    int d = i & 63;
    g_qw4[i] = make_float4(g_qph[(2 * p) * D + d], g_qph[(2 * p + 1) * D + d],
                           0.5f * wvec[d], 0.f);
    if (i == 0) {
        float s = bptr[0];
#pragma unroll
        for (int dd = 0; dd < D; dd++) s += 0.5f * wvec[dd];
        g_bias = s;
    }
}

// ---------------------------------------------------------------------------
// Main fused kernel. Grid = 1024: (rowgroup 0..127) x (split 0..7).
// Block 256 thr = 8 warps x 2 rows = 16 rows; each block does SPAN=256 of N2.
// Score phase: lane owns m-pair; each k smem read feeds 2 rows x 2 m.
// PV phase: p staged in warp-private smem; lane owns a d-pair (4 acc regs).
// sigmoid(z) = 0.5*tanh(z/2)+0.5 folded into halved inputs + bias.
// ---------------------------------------------------------------------------
__global__ __launch_bounds__(256, 2)
void attn_kernel(const float* __restrict__ vglob,    // [N2, D] original v
                 float* __restrict__ att_score) {    // [N1, N2]
    extern __shared__ float sm[];
    // layout (floats): [k0 4096][v0 4096][k1 4096][v1 4096][qws 2048][p 1024]
    float*  kb0 = sm;
    float*  vb0 = sm + 4096;
    float*  kb1 = sm + 8192;
    float*  vb1 = sm + 12288;
    float4* qws = (float4*)(sm + 16384);   // [8 warps][64 d]
    float*  psm = sm + 18432;              // [8 warps][64 m][2 rows]

    const int tid   = threadIdx.x;
    const int warp  = tid >> 5;
    const int lane  = tid & 31;
    const int split = blockIdx.x & (SPLITS - 1);
    const int rg    = blockIdx.x >> 3;
    const int n0    = rg * 16;
    const int r0    = n0 + 2 * warp;
    const int r1    = r0 + 1;
    const int mbase = split * SPAN;

    // prologue: one cp.async group = qws table slice + tile 0 (k, v)
    {
        const float4* src = g_qw4 + rg * 512;          // 8 row-pairs x 64 d, contiguous
        cp_async16(qws + tid,       src + tid);
        cp_async16(qws + tid + 256, src + tid + 256);
        int r = tid >> 4, c = (tid & 15) << 2;
#pragma unroll
        for (int j = 0; j < 4; j++) {
            int rr = r + j * 16;
            cp_async16(kb0 + rr * 64 + c, g_kpTh + rr * N2 + mbase + c);
            cp_async16(vb0 + rr * 64 + c, vglob + (mbase + rr) * D + c);
        }
        cp_commit();
    }
    const float bias = g_bias;

    float2 a0 = make_float2(0.f, 0.f);   // acc row r0, d = 2*lane, 2*lane+1
    float2 a1 = make_float2(0.f, 0.f);   // acc row r1
    float  S0 = 0.f, S1 = 0.f;

    float2* sr0 = (float2*)(att_score + (size_t)r0 * N2 + mbase);
    float2* sr1 = (float2*)(att_score + (size_t)r1 * N2 + mbase);
    float*  pw  = psm + warp * 128;      // warp-private p staging [64 m][2 rows]

    for (int t = 0; t < NT; t++) {
        cp_wait0();
        __syncthreads();   // buffer filled; prev tile consumed by all warps

        const float* kt = (t & 1) ? kb1 : kb0;
        const float* vt = (t & 1) ? vb1 : vb0;

        if (t + 1 < NT) {  // async-load next tile into the other buffer
            float* kn = (t & 1) ? kb0 : kb1;
            float* vn = (t & 1) ? vb0 : vb1;
            int r = tid >> 4, c = (tid & 15) << 2;
            int col0 = mbase + (t + 1) * 64;
#pragma unroll
            for (int j = 0; j < 4; j++) {
                int rr = r + j * 16;
                cp_async16(kn + rr * 64 + c, g_kpTh + rr * N2 + col0 + c);
                cp_async16(vn + rr * 64 + c, vglob + (col0 + rr) * D + c);
            }
            cp_commit();
        }

        // ----- scores: 1 LDS.64 of k feeds 2 rows x 2 m -----
        float s00 = 0.f, s01 = 0.f, s10 = 0.f, s11 = 0.f;
#pragma unroll 8
        for (int d = 0; d < D; d++) {
            float4 qw = qws[warp * 64 + d];                 // uniform broadcast
            float2 kk = ((const float2*)(kt + d * 64))[lane];
            float t00 = tanh_fast(qw.x + kk.x);
            float t01 = tanh_fast(qw.x + kk.y);
            float t10 = tanh_fast(qw.y + kk.x);
            float t11 = tanh_fast(qw.y + kk.y);
            s00 = fmaf(qw.z, t00, s00);
            s01 = fmaf(qw.z, t01, s01);
            s10 = fmaf(qw.z, t10, s10);
            s11 = fmaf(qw.z, t11, s11);
        }
        s00 += bias; s01 += bias; s10 += bias; s11 += bias;
        sr0[t * 32 + lane] = make_float2(s00, s01);
        sr1[t * 32 + lane] = make_float2(s10, s11);

        // ----- softmax weights (scores bounded ~|3|: no running max) -----
        float p00 = __expf(s00), p01 = __expf(s01);
        float p10 = __expf(s10), p11 = __expf(s11);
        S0 += p00 + p01;
        S1 += p10 + p11;

        ((float2*)pw)[2 * lane]     = make_float2(p00, p10);
        ((float2*)pw)[2 * lane + 1] = make_float2(p01, p11);
        __syncwarp();

        // ----- PV: lane owns d-pair; p uniform broadcast, v conflict-free -----
#pragma unroll 8
        for (int m = 0; m < TILE; m++) {
            float2 pp = ((const float2*)pw)[m];             // (p_r0[m], p_r1[m])
            float2 vv = ((const float2*)(vt + m * 64))[lane];
            a0.x = fmaf(pp.x, vv.x, a0.x);
            a0.y = fmaf(pp.x, vv.y, a0.y);
            a1.x = fmaf(pp.y, vv.x, a1.x);
            a1.y = fmaf(pp.y, vv.y, a1.y);
        }
        __syncwarp();   // p buffer consumed before next tile overwrites
    }

    // ----- S reduction over lanes (acc needs none: d-owned) -----
#pragma unroll
    for (int off = 16; off; off >>= 1) {
        S0 += __shfl_xor_sync(0xffffffffu, S0, off);
        S1 += __shfl_xor_sync(0xffffffffu, S1, off);
    }

    ((float2*)(g_accP + ((size_t)split * N1 + r0) * D))[lane] = a0;
    ((float2*)(g_accP + ((size_t)split * N1 + r1) * D))[lane] = a1;
    if (lane == 0) {
        g_Ssum[split * N1 + r0] = S0;
        g_Ssum[split * N1 + r1] = S1;
    }
}

// ---------------------------------------------------------------------------
// Combine splits: out[n][d] = sum_s acc[s][n][d] / sum_s S[s][n]
// ---------------------------------------------------------------------------
__global__ void combine_kernel(float* __restrict__ out) {
    int tid = threadIdx.x;
    int n   = blockIdx.x * 8 + (tid >> 5);
    int d2  = tid & 31;
    float2 a = make_float2(0.f, 0.f);
    float  S = 0.f;
#pragma unroll
    for (int s = 0; s < SPLITS; s++) {
        float2 p = ((const float2*)(g_accP + ((size_t)s * N1 + n) * D))[d2];
        a.x += p.x; a.y += p.y;
        S += g_Ssum[s * N1 + n];
    }
    float r = __fdividef(1.f, S);
    ((float2*)(out + (size_t)n * D))[d2] = make_float2(a.x * r, a.y * r);
}

// ---------------------------------------------------------------------------
extern "C" void kernel_launch(void* const* d_in, const int* in_sizes, int n_in,
                              void* d_out, int out_size) {
    const float* q  = (const float*)d_in[0];
    const float* k  = (const float*)d_in[1];
    const float* v  = (const float*)d_in[2];
    const float* Wq = (const float*)d_in[3];
    const float* bq = (const float*)d_in[4];
    const float* Wk = (const float*)d_in[5];
    const float* bk = (const float*)d_in[6];
    const float* w  = (const float*)d_in[7];
    const float* b  = (const float*)d_in[8];

    float* out       = (float*)d_out;          // [N1, D] first
    float* att_score = out + N1 * D;           // then [N1, N2]

    const int SMEM_BYTES = (4 * 4096 + 2048 + 1024) * (int)sizeof(float);   // 77824
    cudaFuncSetAttribute(attn_kernel, cudaFuncAttributeMaxDynamicSharedMemorySize,
                         SMEM_BYTES);

    prep_kernel<<<2 * 512, 256>>>(q, k, Wq, bq, Wk, bk);
    prep2_kernel<<<256, 256>>>(w, b);
    attn_kernel<<<128 * SPLITS, 256, SMEM_BYTES>>>(v, att_score);
    combine_kernel<<<N1 / 8, 256>>>(out);
}

// round 11
// speedup vs baseline: 2.0025x; 1.0457x over previous
#include <cuda_runtime.h>
#include <cstdint>

#define N1     2048
#define N2     2048
#define D      64
#define TILE   64
#define SPLITS 8
#define SPAN   (N2 / SPLITS)     // 256 m per block
#define NT     (SPAN / TILE)     // 4 tiles per block

// Scratch (allocation-free rule: __device__ globals)
__device__ float  g_qph [N1 * D];          // 0.5*(q@Wq+bq)   row-major [n][d]
__device__ float  g_kpTh[D * N2];          // 0.5*(k@Wk+bk)^T [d][m]
__device__ float4 g_qw4 [(N1 / 2) * D];    // (q_2p/2, q_2p+1/2, w/2, 0)
__device__ float  g_bias;                  // b + sum_d w_d/2
__device__ float  g_accP[SPLITS * N1 * D]; // partial PV accumulators
__device__ float  g_Ssum[SPLITS * N1];     // partial exp-sums

__device__ __forceinline__ float tanh_fast(float x) {
    float y;
    asm("tanh.approx.f32 %0, %1;" : "=f"(y) : "f"(x));
    return y;
}
__device__ __forceinline__ void cp_async16(void* saddr, const void* gptr) {
    uint32_t s = (uint32_t)__cvta_generic_to_shared(saddr);
    asm volatile("cp.async.cg.shared.global [%0], [%1], 16;" :: "r"(s), "l"(gptr));
}
__device__ __forceinline__ void cp_commit() { asm volatile("cp.async.commit_group;"); }
__device__ __forceinline__ void cp_wait0()  { asm volatile("cp.async.wait_group 0;" ::: "memory"); }

// ---------------------------------------------------------------------------
// Prep: halved projections; 4 outputs per thread (4 independent FMA chains)
// ---------------------------------------------------------------------------
__global__ void prep_kernel(const float* __restrict__ q,
                            const float* __restrict__ k,
                            const float* __restrict__ Wq, const float* __restrict__ bq,
                            const float* __restrict__ Wk, const float* __restrict__ bk) {
    int job = blockIdx.x >> 7;                              // 128 blocks per job
    int i   = ((blockIdx.x & 127) << 8) + threadIdx.x;      // 0 .. 32767
    int n   = i >> 4;
    int d0  = (i & 15) << 2;

    const float* x  = job ? k  : q;
    const float* W  = job ? Wk : Wq;
    const float* bb = job ? bk : bq;

    float4 acc = make_float4(0.f, 0.f, 0.f, 0.f);
#pragma unroll 16
    for (int kk = 0; kk < D; kk++) {
        float  xs = x[n * D + kk];                          // warp-broadcast
        float4 w4 = *(const float4*)&W[kk * D + d0];        // coalesced
        acc.x = fmaf(xs, w4.x, acc.x);
        acc.y = fmaf(xs, w4.y, acc.y);
        acc.z = fmaf(xs, w4.z, acc.z);
        acc.w = fmaf(xs, w4.w, acc.w);
    }
    float4 b4 = *(const float4*)&bb[d0];
    float4 r  = make_float4(0.5f * (acc.x + b4.x), 0.5f * (acc.y + b4.y),
                            0.5f * (acc.z + b4.z), 0.5f * (acc.w + b4.w));
    if (job == 0) {
        *(float4*)&g_qph[n * D + d0] = r;
    } else {
        g_kpTh[(d0 + 0) * N2 + n] = r.x;
        g_kpTh[(d0 + 1) * N2 + n] = r.y;
        g_kpTh[(d0 + 2) * N2 + n] = r.z;
        g_kpTh[(d0 + 3) * N2 + n] = r.w;
    }
}

// ---------------------------------------------------------------------------
// Prep2: interleaved (q-pair, w) float4 table + scalar bias
// ---------------------------------------------------------------------------
__global__ void prep2_kernel(const float* __restrict__ wvec,
                             const float* __restrict__ bptr) {
    int i = blockIdx.x * 256 + threadIdx.x;   // 0 .. 65535
    int p = i >> 6;
    int d = i & 63;
    g_qw4[i] = make_float4(g_qph[(2 * p) * D + d], g_qph[(2 * p + 1) * D + d],
                           0.5f * wvec[d], 0.f);
    if (i == 0) {
        float s = bptr[0];
#pragma unroll
        for (int dd = 0; dd < D; dd++) s += 0.5f * wvec[dd];
        g_bias = s;
    }
}

// ---------------------------------------------------------------------------
// Main fused kernel. Grid = 1024: (rowgroup 0..127) x (split 0..7).
// Block 256 thr = 8 warps x 2 rows = 16 rows; block does SPAN=256 of N2.
// Software pipeline: PV(t-1) interleaved into score loop of tile t, so the
// MUFU (tanh) pipe binds uniformly and FMA/LDS hide beneath it.
// k: 2-buffer ring. v: 3-buffer ring (tile x lives in vb[x%3]).
// sigmoid(z) = 0.5*tanh(z/2)+0.5 folded into halved inputs + bias.
// ---------------------------------------------------------------------------
__global__ __launch_bounds__(256, 2)
void attn_kernel(const float* __restrict__ vglob,    // [N2, D] original v
                 float* __restrict__ att_score) {    // [N1, N2]
    extern __shared__ float sm[];
    // floats: [kb0 4096][kb1 4096][vb0 4096][vb1 4096][vb2 4096][qws 2048][p 1024]
    float*  kb0 = sm;
    float*  kb1 = sm + 4096;
    float*  vbb = sm + 8192;               // 3 x 4096
    float4* qws = (float4*)(sm + 20480);   // [8 warps][64 d]
    float*  psm = sm + 22528;              // [8 warps][64 m][2 rows]

    const int tid   = threadIdx.x;
    const int warp  = tid >> 5;
    const int lane  = tid & 31;
    const int split = blockIdx.x & (SPLITS - 1);
    const int rg    = blockIdx.x >> 3;
    const int n0    = rg * 16;
    const int r0    = n0 + 2 * warp;
    const int r1    = r0 + 1;
    const int mbase = split * SPAN;

    // prologue: one cp.async group = qws table slice + tile 0 (k, v)
    {
        const float4* src = g_qw4 + rg * 512;
        cp_async16(qws + tid,       src + tid);
        cp_async16(qws + tid + 256, src + tid + 256);
        int r = tid >> 4, c = (tid & 15) << 2;
#pragma unroll
        for (int j = 0; j < 4; j++) {
            int rr = r + j * 16;
            cp_async16(kb0 + rr * 64 + c, g_kpTh + rr * N2 + mbase + c);
            cp_async16(vbb + rr * 64 + c, vglob + (mbase + rr) * D + c);
        }
        cp_commit();
    }
    const float bias = g_bias;

    float2 a0 = make_float2(0.f, 0.f);   // acc row r0, d = 2*lane, 2*lane+1
    float2 a1 = make_float2(0.f, 0.f);   // acc row r1
    float  S0 = 0.f, S1 = 0.f;

    float2* sr0 = (float2*)(att_score + (size_t)r0 * N2 + mbase);
    float2* sr1 = (float2*)(att_score + (size_t)r1 * N2 + mbase);
    float*  pw  = psm + warp * 128;      // warp-private p staging [64 m][2 rows]

    for (int t = 0; t < NT; t++) {
        cp_wait0();
        __syncthreads();   // tile t buffers filled; all warps done with t-1

        const float* kt = (t & 1) ? kb1 : kb0;

        if (t + 1 < NT) {  // prefetch tile t+1: k -> other k buf, v -> vb[(t+1)%3]
            float* kn = (t & 1) ? kb0 : kb1;
            float* vn = vbb + ((t + 1) % 3) * 4096;
            int r = tid >> 4, c = (tid & 15) << 2;
            int col0 = mbase + (t + 1) * 64;
#pragma unroll
            for (int j = 0; j < 4; j++) {
                int rr = r + j * 16;
                cp_async16(kn + rr * 64 + c, g_kpTh + rr * N2 + col0 + c);
                cp_async16(vn + rr * 64 + c, vglob + (col0 + rr) * D + c);
            }
            cp_commit();
        }

        float s00 = 0.f, s01 = 0.f, s10 = 0.f, s11 = 0.f;

        if (t == 0) {
            // scores only (no previous tile to accumulate)
#pragma unroll 8
            for (int d = 0; d < D; d++) {
                float4 qw = qws[warp * 64 + d];
                float2 kk = ((const float2*)(kt + d * 64))[lane];
                float t00 = tanh_fast(qw.x + kk.x);
                float t01 = tanh_fast(qw.x + kk.y);
                float t10 = tanh_fast(qw.y + kk.x);
                float t11 = tanh_fast(qw.y + kk.y);
                s00 = fmaf(qw.z, t00, s00);
                s01 = fmaf(qw.z, t01, s01);
                s10 = fmaf(qw.z, t10, s10);
                s11 = fmaf(qw.z, t11, s11);
            }
        } else {
            // fused: scores(t) + PV(t-1); MUFU binds, FMA/LDS hide under it
            const float* vprev = vbb + ((t - 1) % 3) * 4096;
#pragma unroll 8
            for (int d = 0; d < D; d++) {
                float4 qw = qws[warp * 64 + d];
                float2 kk = ((const float2*)(kt + d * 64))[lane];
                float t00 = tanh_fast(qw.x + kk.x);
                float t01 = tanh_fast(qw.x + kk.y);
                float t10 = tanh_fast(qw.y + kk.x);
                float t11 = tanh_fast(qw.y + kk.y);
                s00 = fmaf(qw.z, t00, s00);
                s01 = fmaf(qw.z, t01, s01);
                s10 = fmaf(qw.z, t10, s10);
                s11 = fmaf(qw.z, t11, s11);
                // PV(t-1), m = d
                float2 pp = ((const float2*)pw)[d];             // broadcast
                float2 vv = ((const float2*)(vprev + d * 64))[lane];
                a0.x = fmaf(pp.x, vv.x, a0.x);
                a0.y = fmaf(pp.x, vv.y, a0.y);
                a1.x = fmaf(pp.y, vv.x, a1.x);
                a1.y = fmaf(pp.y, vv.y, a1.y);
            }
        }
        s00 += bias; s01 += bias; s10 += bias; s11 += bias;
        sr0[t * 32 + lane] = make_float2(s00, s01);
        sr1[t * 32 + lane] = make_float2(s10, s11);

        // softmax weights (scores bounded ~|3|: no running max)
        float p00 = __expf(s00), p01 = __expf(s01);
        float p10 = __expf(s10), p11 = __expf(s11);
        S0 += p00 + p01;
        S1 += p10 + p11;

        __syncwarp();      // PV(t-1) reads of pw complete across the warp
        ((float2*)pw)[2 * lane]     = make_float2(p00, p10);
        ((float2*)pw)[2 * lane + 1] = make_float2(p01, p11);
        __syncwarp();      // pw(t) visible to all lanes
    }

    // epilogue: PV for last tile
    {
        const float* vlast = vbb + ((NT - 1) % 3) * 4096;
#pragma unroll 8
        for (int m = 0; m < TILE; m++) {
            float2 pp = ((const float2*)pw)[m];
            float2 vv = ((const float2*)(vlast + m * 64))[lane];
            a0.x = fmaf(pp.x, vv.x, a0.x);
            a0.y = fmaf(pp.x, vv.y, a0.y);
            a1.x = fmaf(pp.y, vv.x, a1.x);
            a1.y = fmaf(pp.y, vv.y, a1.y);
        }
    }

    // S reduction over lanes (acc needs none: d-owned)
#pragma unroll
    for (int off = 16; off; off >>= 1) {
        S0 += __shfl_xor_sync(0xffffffffu, S0, off);
        S1 += __shfl_xor_sync(0xffffffffu, S1, off);
    }

    ((float2*)(g_accP + ((size_t)split * N1 + r0) * D))[lane] = a0;
    ((float2*)(g_accP + ((size_t)split * N1 + r1) * D))[lane] = a1;
    if (lane == 0) {
        g_Ssum[split * N1 + r0] = S0;
        g_Ssum[split * N1 + r1] = S1;
    }
}

// ---------------------------------------------------------------------------
// Combine splits: thread owns a d-quad; 8 independent LDG.128
// ---------------------------------------------------------------------------
__global__ void combine_kernel(float* __restrict__ out) {
    int i  = blockIdx.x * 256 + threadIdx.x;   // 0 .. 32767
    int n  = i >> 4;
    int d0 = (i & 15) << 2;
    float4 a = make_float4(0.f, 0.f, 0.f, 0.f);
    float  S = 0.f;
#pragma unroll
    for (int s = 0; s < SPLITS; s++) {
        float4 p = *(const float4*)&g_accP[((size_t)s * N1 + n) * D + d0];
        a.x += p.x; a.y += p.y; a.z += p.z; a.w += p.w;
        S += g_Ssum[s * N1 + n];
    }
    float r = __fdividef(1.f, S);
    *(float4*)&out[(size_t)n * D + d0] = make_float4(a.x * r, a.y * r, a.z * r, a.w * r);
}

// ---------------------------------------------------------------------------
extern "C" void kernel_launch(void* const* d_in, const int* in_sizes, int n_in,
                              void* d_out, int out_size) {
    const float* q  = (const float*)d_in[0];
    const float* k  = (const float*)d_in[1];
    const float* v  = (const float*)d_in[2];
    const float* Wq = (const float*)d_in[3];
    const float* bq = (const float*)d_in[4];
    const float* Wk = (const float*)d_in[5];
    const float* bk = (const float*)d_in[6];
    const float* w  = (const float*)d_in[7];
    const float* b  = (const float*)d_in[8];

    float* out       = (float*)d_out;          // [N1, D] first
    float* att_score = out + N1 * D;           // then [N1, N2]

    const int SMEM_BYTES = (5 * 4096 + 2048 + 1024) * (int)sizeof(float);   // 94208
    cudaFuncSetAttribute(attn_kernel, cudaFuncAttributeMaxDynamicSharedMemorySize,
                         SMEM_BYTES);

    prep_kernel<<<256, 256>>>(q, k, Wq, bq, Wk, bk);
    prep2_kernel<<<256, 256>>>(w, b);
    attn_kernel<<<128 * SPLITS, 256, SMEM_BYTES>>>(v, att_score);
    combine_kernel<<<128, 256>>>(out);
}